// round 15
// baseline (speedup 1.0000x reference)
#include <cuda_runtime.h>
#include <math.h>

// ---------------------------------------------------------------------------
// FraudDetectionNet — SINGLE fused kernel.
//
// qcontrib_p = t01^T C_p t23, b_q=(1,cos p_q,sin p_q).
// C_p[s] = sum_m c_p[m] K[m][s];  K collapsed to 16 XOR/sign terms:
//   K[m][s] = (1/16) sum_n (-1)^{popc(n&neg)}
//             (Ur[m,n]Ur[m,n^mask] + Ui[m,n]Ui[m,n^mask]),
//   mask_q=(s_q==2), neg_q=(s_q==1).  c_p[m] folds Z + classifier weights.
//
// Prologue (per block, aliased into the image-staging smem): build KsT[s][m],
// cpm[p][m], then C (rows of 9 padded to 12; f32x2 pair dot over m).
// Hot loop: 512 thr, 64 images/block (2/thread: lane, lane+32), two
// half-image staging phases (stride 394 -> conflict-free LDS), bilinear form
// evaluated with fma.rn.f32x2 (adjacent C columns paired; epilogue stays
// lane-packed, one lane-sum per image at loop exit).
// ---------------------------------------------------------------------------

#define NPATCH   196
#define CROW     12          // padded row length (9 used) -> 16B-aligned rows
#define CPP      (9*CROW)    // 108 floats per patch
#define NIMG     64
#define NTHREADS 512
#define NWARPS   16
#define XS2      394         // half-image stride (197 odd -> conflict-free)
#define SMEM_BYTES ((NPATCH*CPP + NIMG*XS2) * 4)

typedef unsigned long long u64;

__device__ __forceinline__ u64 pk2(float lo, float hi) {
    u64 r; asm("mov.b64 %0,{%1,%2};" : "=l"(r) : "f"(lo), "f"(hi)); return r;
}
__device__ __forceinline__ float2 upk2(u64 v) {
    float2 f; asm("mov.b64 {%0,%1},%2;" : "=f"(f.x), "=f"(f.y) : "l"(v)); return f;
}
__device__ __forceinline__ u64 fma2_(u64 a, u64 b, u64 c) {
    u64 d; asm("fma.rn.f32x2 %0,%1,%2,%3;" : "=l"(d) : "l"(a), "l"(b), "l"(c)); return d;
}
__device__ __forceinline__ u64 mul2_(u64 a, u64 b) {
    u64 d; asm("mul.rn.f32x2 %0,%1,%2;" : "=l"(d) : "l"(a), "l"(b)); return d;
}
__device__ __forceinline__ u64 add2_(u64 a, u64 b) {
    u64 d; asm("add.rn.f32x2 %0,%1,%2;" : "=l"(d) : "l"(a), "l"(b)); return d;
}

__global__ void __launch_bounds__(NTHREADS, 1)
mainK(const float* __restrict__ x,
      const float* __restrict__ w_in,   const float* __restrict__ b_in,
      const float* __restrict__ scale_in, const float* __restrict__ shift_in,
      const float* __restrict__ Wc,     const float* __restrict__ bc,
      const float* __restrict__ scalec, const float* __restrict__ shiftc,
      const float* __restrict__ w_out,  const float* __restrict__ b_out,
      const float* __restrict__ Ure,    const float* __restrict__ Uim,
      const float* __restrict__ w_cls,  const float* __restrict__ b_cls,
      float* __restrict__ out, int B, int L)
{
    extern __shared__ float sm[];
    float* Cs = sm;                       // NPATCH*CPP floats (84.7KB)
    float* xs = sm + NPATCH * CPP;        // NIMG*XS2 floats (100.9KB)
    // prologue aliases inside xs (overwritten later by image staging):
    float* ur  = xs;                      // 256
    float* ui  = xs + 256;                // 256
    float* KsT = xs + 512;                // 81*16 = 1296  (offset 2048B, 8B ok)
    float* cpm = xs + 512 + 1296;         // 196*16 = 3136 (offset 7232B, 8B ok)
    __shared__ float rq[NWARPS][NIMG];
    __shared__ float sS1[NIMG], sS2[NIMG];

    const int tid  = threadIdx.x;
    const int w    = tid >> 5;
    const int lane = tid & 31;
    const int img_base = blockIdx.x * NIMG;
    int nimg = B - img_base;
    if (nimg > NIMG) nimg = NIMG;

    // ---- prologue: build C in smem --------------------------------------
    if (tid < 256) ur[tid] = Ure[tid];
    else           ui[tid - 256] = Uim[tid - 256];
    for (int e = tid; e < NPATCH * 16; e += NTHREADS) {
        int p = e >> 4, m = e & 15;
        const float* wp = w_cls + 1 + 4 * p;
        float acc = 0.f;
#pragma unroll
        for (int q = 0; q < 4; ++q)
            acc = fmaf(1.f - 2.f * (float)((m >> (3 - q)) & 1), wp[q], acc);
        cpm[e] = acc;
    }
    __syncthreads();

    for (int e = tid; e < 81 * 16; e += NTHREADS) {
        int s = e >> 4, m = e & 15;
        int s3 = s % 3, r = s / 3;
        int s2 = r % 3; r /= 3;
        int s1 = r % 3, s0 = r / 3;
        int mask = ((int)(s0 == 2) << 3) | ((int)(s1 == 2) << 2)
                 | ((int)(s2 == 2) << 1) | (int)(s3 == 2);
        int neg  = ((int)(s0 == 1) << 3) | ((int)(s1 == 1) << 2)
                 | ((int)(s2 == 1) << 1) | (int)(s3 == 1);
        const float* urm = ur + m * 16;
        const float* uim = ui + m * 16;
        float acc = 0.f;
#pragma unroll
        for (int n = 0; n < 16; ++n) {
            float v = urm[n] * urm[n ^ mask] + uim[n] * uim[n ^ mask];
            acc += (__popc(n & neg) & 1) ? -v : v;
        }
        KsT[e] = acc * 0.0625f;           // KsT[s*16+m]
    }
    __syncthreads();

    for (int e = tid; e < NPATCH * CPP; e += NTHREADS) {
        int p = e / CPP, r = e - p * CPP;
        int i = r / CROW, j = r - i * CROW;
        float vout = 0.f;
        if (j < 9) {
            int k = i * 9 + j;
            const u64* cp = (const u64*)(cpm + p * 16);
            const u64* kt = (const u64*)(KsT + k * 16);
            u64 acc = mul2_(cp[0], kt[0]);
#pragma unroll
            for (int mp = 1; mp < 8; ++mp) acc = fma2_(cp[mp], kt[mp], acc);
            float2 f = upk2(acc);
            vout = f.x + f.y;
        }
        Cs[e] = vout;
    }
    __syncthreads();

    // ---- main loop: two half-image phases -------------------------------
    const bool hasA = lane < nimg;
    const bool hasB = (lane + 32) < nimg;
    const float* xsA = xs + lane * XS2;
    const float* xsB = xs + (lane + 32) * XS2;

    u64 qaccA = pk2(0.f, 0.f), qaccB = pk2(0.f, 0.f);
    float ls1[4] = {0.f, 0.f, 0.f, 0.f};
    float ls2[4] = {0.f, 0.f, 0.f, 0.f};

    const int pstartL = (w * 98) / NWARPS;
    const int pendL   = ((w + 1) * 98) / NWARPS;

    for (int h = 0; h < 2; ++h) {
        if (h) __syncthreads();

        // stage half-image h for images w, w+16, w+32, w+48 + stats
#pragma unroll
        for (int j = 0; j < 4; ++j) {
            int img = w + 16 * j;
            if (img < nimg) {
                const float4* src = (const float4*)(x + (size_t)(img_base + img) * 784)
                                    + 98 * h;
                float* dst = xs + img * XS2;
                for (int k = lane; k < 98; k += 32) {
                    float4 v = src[k];
                    dst[4 * k + 0] = v.x; dst[4 * k + 1] = v.y;
                    dst[4 * k + 2] = v.z; dst[4 * k + 3] = v.w;
                    ls1[j] += (v.x + v.y) + (v.z + v.w);
                    ls2[j] = fmaf(v.x, v.x, fmaf(v.y, v.y,
                             fmaf(v.z, v.z, fmaf(v.w, v.w, ls2[j]))));
                }
            }
        }
        __syncthreads();

        int pr = pstartL / 14, pc = pstartL - pr * 14;
        int loff = pr * 56 + pc * 2;

        float2 tpA = *(const float2*)(xsA + loff);
        float2 btA = *(const float2*)(xsA + loff + 28);
        float2 tpB = *(const float2*)(xsB + loff);
        float2 btB = *(const float2*)(xsB + loff + 28);

        for (int p = pstartL; p < pendL; ++p) {
            float2 cA0 = tpA, cA1 = btA, cB0 = tpB, cB1 = btB;
            if (++pc == 14) { pc = 0; loff += 30; } else { loff += 2; }
            if (p + 1 < pendL) {
                tpA = *(const float2*)(xsA + loff);
                btA = *(const float2*)(xsA + loff + 28);
                tpB = *(const float2*)(xsB + loff);
                btB = *(const float2*)(xsB + loff + 28);
            }

            // image A trig + packed t-vectors
            float a0c, a0s, a1c, a1s, a2c, a2s, a3c, a3s;
            __sincosf(cA0.x, &a0s, &a0c);
            __sincosf(cA0.y, &a1s, &a1c);
            __sincosf(cA1.x, &a2s, &a2c);
            __sincosf(cA1.y, &a3s, &a3c);
            u64 tA0 = pk2(1.f, a3c);                       // (1, c3)
            u64 tA1 = pk2(a3s, a2c);                       // (s3, c2)
            u64 PsA = pk2(a2s, a2s);
            u64 tA2 = mul2_(pk2(a2c, a2c), pk2(a3c, a3s)); // (c2c3, c2s3)
            u64 tA3 = mul2_(PsA, tA0);                     // (s2, s2c3)
            u64 tA4 = mul2_(PsA, pk2(a3s, 0.f));           // (s2s3, 0)
            u64 c1A = pk2(a1c, a1c), s1A = pk2(a1s, a1s);
            u64 c0A = pk2(a0c, a0c), s0A = pk2(a0s, a0s);

            // image B trig + packed t-vectors
            float b0c, b0s, b1c, b1s, b2c, b2s, b3c, b3s;
            __sincosf(cB0.x, &b0s, &b0c);
            __sincosf(cB0.y, &b1s, &b1c);
            __sincosf(cB1.x, &b2s, &b2c);
            __sincosf(cB1.y, &b3s, &b3c);
            u64 tB0 = pk2(1.f, b3c);
            u64 tB1 = pk2(b3s, b2c);
            u64 PsB = pk2(b2s, b2s);
            u64 tB2 = mul2_(pk2(b2c, b2c), pk2(b3c, b3s));
            u64 tB3 = mul2_(PsB, tB0);
            u64 tB4 = mul2_(PsB, pk2(b3s, 0.f));
            u64 c1B = pk2(b1c, b1c), s1B = pk2(b1s, b1s);
            u64 c0B = pk2(b0c, b0c), s0B = pk2(b0s, b0s);

            const float* Crow = Cs + (size_t)(98 * h + p) * CPP;
            u64 EA0, EA1, EA2, EB0, EB1, EB2;
#pragma unroll
            for (int g = 0; g < 3; ++g) {
                u64 dA0, dA1, dA2, dB0, dB1, dB2;
#pragma unroll
                for (int rr = 0; rr < 3; ++rr) {
                    const ulonglong2* r2 = (const ulonglong2*)Crow;
                    ulonglong2 L0 = r2[0];
                    ulonglong2 L1 = r2[1];
                    u64 p4 = ((const u64*)Crow)[4];
                    u64 a = mul2_(L0.x, tA0);
                    a = fma2_(L0.y, tA1, a);
                    a = fma2_(L1.x, tA2, a);
                    a = fma2_(L1.y, tA3, a);
                    a = fma2_(p4,  tA4, a);
                    u64 b = mul2_(L0.x, tB0);
                    b = fma2_(L0.y, tB1, b);
                    b = fma2_(L1.x, tB2, b);
                    b = fma2_(L1.y, tB3, b);
                    b = fma2_(p4,  tB4, b);
                    if (rr == 0) { dA0 = a; dB0 = b; }
                    else if (rr == 1) { dA1 = a; dB1 = b; }
                    else { dA2 = a; dB2 = b; }
                    Crow += CROW;
                }
                u64 ea = fma2_(s1A, dA2, fma2_(c1A, dA1, dA0));
                u64 eb = fma2_(s1B, dB2, fma2_(c1B, dB1, dB0));
                if (g == 0) { EA0 = ea; EB0 = eb; }
                else if (g == 1) { EA1 = ea; EB1 = eb; }
                else { EA2 = ea; EB2 = eb; }
            }
            qaccA = add2_(qaccA, fma2_(s0A, EA2, fma2_(c0A, EA1, EA0)));
            qaccB = add2_(qaccB, fma2_(s0B, EB2, fma2_(c0B, EB1, EB0)));
        }
    }

    // ---- reductions + per-image MLP epilogue ----------------------------
#pragma unroll
    for (int j = 0; j < 4; ++j) {
        float a = ls1[j], b = ls2[j];
#pragma unroll
        for (int o = 16; o > 0; o >>= 1) {
            a += __shfl_down_sync(0xffffffffu, a, o);
            b += __shfl_down_sync(0xffffffffu, b, o);
        }
        if (lane == 0) { sS1[w + 16 * j] = a; sS2[w + 16 * j] = b; }
    }
    float2 qfA = upk2(qaccA);
    float2 qfB = upk2(qaccB);
    rq[w][lane]      = hasA ? (qfA.x + qfA.y) : 0.f;
    rq[w][lane + 32] = hasB ? (qfB.x + qfB.y) : 0.f;
    __syncthreads();

    if (tid < NIMG && tid < nimg) {
        float Q = 0.f;
#pragma unroll
        for (int k = 0; k < NWARPS; ++k) Q += rq[k][tid];
        float S1 = sS1[tid], S2 = sS2[tid];
        float mean = S1 * (1.f / 784.f);
        float var  = (S2 - S1 * S1 * (1.f / 784.f)) * (1.f / 783.f);
        float stdv = sqrtf(fmaxf(var, 0.f));
        float h0 = tanhf(fmaf(mean, w_in[0], fmaf(stdv, w_in[1], b_in[0]))) * scale_in[0] + shift_in[0];
        float h1 = tanhf(fmaf(mean, w_in[2], fmaf(stdv, w_in[3], b_in[1]))) * scale_in[1] + shift_in[1];
        for (int i = 0; i < L; ++i) {
            float n0 = tanhf(fmaf(h0, Wc[i*4+0], fmaf(h1, Wc[i*4+1], bc[i*2+0]))) * scalec[i*2+0] + shiftc[i*2+0];
            float n1 = tanhf(fmaf(h0, Wc[i*4+2], fmaf(h1, Wc[i*4+3], bc[i*2+1]))) * scalec[i*2+1] + shiftc[i*2+1];
            h0 = n0; h1 = n1;
        }
        float cls   = fmaf(h0, w_out[0], fmaf(h1, w_out[1], b_out[0]));
        float logit = fmaf(cls, w_cls[0], Q + b_cls[0]);
        out[img_base + tid] = 1.f / (1.f + expf(-logit));
    }
}

extern "C" void kernel_launch(void* const* d_in, const int* in_sizes, int n_in,
                              void* d_out, int out_size) {
    const float* x        = (const float*)d_in[0];
    const float* w_in     = (const float*)d_in[1];
    const float* b_in     = (const float*)d_in[2];
    const float* scale_in = (const float*)d_in[3];
    const float* shift_in = (const float*)d_in[4];
    const float* Wc       = (const float*)d_in[5];
    const float* bc       = (const float*)d_in[6];
    const float* scalec   = (const float*)d_in[7];
    const float* shiftc   = (const float*)d_in[8];
    const float* w_out    = (const float*)d_in[9];
    const float* b_out    = (const float*)d_in[10];
    const float* U_re     = (const float*)d_in[11];
    const float* U_im     = (const float*)d_in[12];
    const float* w_cls    = (const float*)d_in[13];
    const float* b_cls    = (const float*)d_in[14];
    float* out = (float*)d_out;

    int B = in_sizes[0] / 784;
    int L = in_sizes[5] / 4;

    cudaFuncSetAttribute(mainK, cudaFuncAttributeMaxDynamicSharedMemorySize, SMEM_BYTES);

    mainK<<<(B + NIMG - 1) / NIMG, NTHREADS, SMEM_BYTES>>>(
        x, w_in, b_in, scale_in, shift_in, Wc, bc, scalec, shiftc,
        w_out, b_out, U_re, U_im, w_cls, b_cls, out, B, L);
}